// round 13
// baseline (speedup 1.0000x reference)
#include <cuda_runtime.h>
#include <cuda_fp16.h>
#include <cstdint>

#define Bv 8
#define Cv 64
#define Hv 256
#define Wv 256
#define HW 65536
#define EPSV 1e-5f

// ---------------- scratch (no allocations allowed) ----------------
__device__ float g_colsum2[2][Bv * Cv * Wv];   // h-half partial column sums
__device__ float g_fsum2[2][Bv * Cv];          // w-half partial f_sum dots
// weight fragments (fp16): [cc(4)][tap(9)][mt(4)][lane(32)] -> uint4 (a0..a3)
__device__ uint4 g_wfrag[4 * 9 * 4 * 32];

// ---------------- helpers ----------------
__device__ __forceinline__ uint32_t hpack(float lo, float hi) {
    __half2 t = __floats2half2_rn(lo, hi);     // x=lo, y=hi
    return *reinterpret_cast<uint32_t*>(&t);
}
__device__ __forceinline__ void mma_f16(float* c, uint4 a, uint32_t b0, uint32_t b1) {
    asm volatile(
        "mma.sync.aligned.m16n8k16.row.col.f32.f16.f16.f32 "
        "{%0,%1,%2,%3}, {%4,%5,%6,%7}, {%8,%9}, {%0,%1,%2,%3};"
        : "+f"(c[0]), "+f"(c[1]), "+f"(c[2]), "+f"(c[3])
        : "r"(a.x), "r"(a.y), "r"(a.z), "r"(a.w), "r"(b0), "r"(b1));
}

// ---------------- kernel 1: half-column sums of x  +  weight fragment prep ----------------
// blocks [0,1024): colsum half; seg = bid>>9, (b,c) = bid&511, h in [seg*128, seg*128+128)
// blocks [1024,1042): wfrag (18 blocks x 8 warps = 144 combos)
__global__ void k_colsum_wfrag(const float* __restrict__ x,
                               const float* __restrict__ wv) {
    if (blockIdx.x < 1024) {
        int seg = blockIdx.x >> 9;
        int bc = blockIdx.x & 511;
        int w = threadIdx.x;
        const float* p = x + (size_t)bc * HW + (size_t)seg * 128 * Wv + w;
        float s0 = 0.f, s1 = 0.f, s2 = 0.f, s3 = 0.f;
        #pragma unroll 4
        for (int h = 0; h < 128; h += 4) {
            s0 += p[(h + 0) * Wv]; s1 += p[(h + 1) * Wv];
            s2 += p[(h + 2) * Wv]; s3 += p[(h + 3) * Wv];
        }
        g_colsum2[seg][bc * Wv + w] = (s0 + s1) + (s2 + s3);
    } else {
        int wid = threadIdx.x >> 5, lane = threadIdx.x & 31;
        int combo = (blockIdx.x - 1024) * 8 + wid;
        int cc = combo / 36, r = combo % 36, tap = r >> 2, mt = r & 3;
        int tig = lane & 3, g = lane >> 2;
        uint32_t h[4];
        #pragma unroll
        for (int rsel = 0; rsel < 4; rsel++) {
            int row = g + (rsel & 1) * 8;
            int k = 2 * tig + (rsel >> 1) * 8;
            int cout = mt * 16 + row;
            float e0 = wv[(size_t)cout * 576 + (cc * 16 + k) * 9 + tap];
            float e1 = wv[(size_t)cout * 576 + (cc * 16 + k + 1) * 9 + tap];
            h[rsel] = hpack(e0, e1);
        }
        g_wfrag[(size_t)combo * 32 + lane] = make_uint4(h[0], h[1], h[2], h[3]);
    }
}

// ---------------- kernel 2: partial f_sum via row-sum identity ----------------
// grid (64 c, 8 b, 2 w-half), 128 threads; w = wh*128 + tid.
// sq/sk need signals at wp = w+dw-1 (global w index; cross-half reads fine).
__global__ void k_fsum(const float* __restrict__ x, const float* __restrict__ wq,
                       const float* __restrict__ wk) {
    int c = blockIdx.x, b = blockIdx.y, wh = blockIdx.z;
    int tid = threadIdx.x;
    int w = wh * 128 + tid;
    __shared__ float wqs[576], wks[576], red[128];
    for (int i = tid; i < 576; i += 128) {
        wqs[i] = wq[c * 576 + i];
        wks[i] = wk[c * 576 + i];
    }
    __syncthreads();
    float sq = 0.f, sk = 0.f;
    for (int ci = 0; ci < Cv; ci++) {
        const float* S0 = g_colsum2[0] + (b * Cv + ci) * Wv;
        const float* S1 = g_colsum2[1] + (b * Cv + ci) * Wv;
        const float* xf = x + (size_t)(b * Cv + ci) * HW;           // row 0
        const float* xl = xf + (Hv - 1) * Wv;                       // row H-1
        const float* q9 = wqs + ci * 9;
        const float* K9 = wks + ci * 9;
        #pragma unroll
        for (int dw = 0; dw < 3; dw++) {
            int wp = w + dw - 1;
            if ((unsigned)wp < (unsigned)Wv) {
                float s = S0[wp] + S1[wp], t = xl[wp], f = xf[wp];
                float q0 = q9[dw], q1 = q9[3 + dw], q2 = q9[6 + dw];
                float k0 = K9[dw], k1 = K9[3 + dw], k2 = K9[6 + dw];
                sq += s * (q0 + q1 + q2) - t * q0 - f * q2;
                sk += s * (k0 + k1 + k2) - t * k0 - f * k2;
            }
        }
    }
    red[tid] = sq * sk;
    __syncthreads();
    for (int s = 64; s > 0; s >>= 1) {
        if (tid < s) red[tid] += red[tid + s];
        __syncthreads();
    }
    if (tid == 0) g_fsum2[wh][b * Cv + c] = red[0] * 0.0625f;   // 1/sqrt(256)
}

// ---------------- kernel 3: fp16 mma.sync implicit-GEMM conv + softmax + epilogue ----------------
// CTA: b x (4 out rows) x (32 out cols). M=64 couts, N=128.
// Row-major B reuse: loop dw -> wg -> input row r; each B load feeds up to 2 MMAs.
__global__ void __launch_bounds__(256, 3)
k_conv(const float* __restrict__ x,
       const float* __restrict__ gamma, const float* __restrict__ beta,
       const float* __restrict__ rmean, const float* __restrict__ rvar,
       float* __restrict__ out) {
    __shared__ uint32_t xs[2][1920];          // 2 x 6*8*40
    __shared__ float sc[64];
    const int tid = threadIdx.x;
    const int lane = tid & 31, wid = tid >> 5;
    const int tig = lane & 3, g = lane >> 2;
    const int mt = wid >> 1, nh = wid & 1;
    const int h0 = blockIdx.x * 4;
    const int w0 = blockIdx.y * 32;
    const int bz = blockIdx.z;

    // ---- inline softmax over 64 channels (warp 0); sum the two w-half partials ----
    if (wid == 0) {
        float va = g_fsum2[0][bz * Cv + lane] + g_fsum2[1][bz * Cv + lane];
        float vb = g_fsum2[0][bz * Cv + 32 + lane] + g_fsum2[1][bz * Cv + 32 + lane];
        float m = fmaxf(va, vb);
        #pragma unroll
        for (int off = 16; off > 0; off >>= 1)
            m = fmaxf(m, __shfl_xor_sync(0xFFFFFFFFu, m, off));
        float ea = expf(va - m), eb = expf(vb - m);
        float s = ea + eb;
        #pragma unroll
        for (int off = 16; off > 0; off >>= 1)
            s += __shfl_xor_sync(0xFFFFFFFFu, s, off);
        sc[lane] = ea / s;
        sc[lane + 32] = eb / s;
    }

    // ---- per-thread tile-load geometry (hoisted; no divisions in loop) ----
    bool sval[2];
    bool sact[2];
    const float* sptr[2];
    uint32_t soff[2];
    #pragma unroll
    for (int i = 0; i < 2; i++) {
        int idx = tid + 256 * i;
        sval[i] = idx < 480;
        sact[i] = false;
        sptr[i] = x;
        soff[i] = 0;
        if (sval[i]) {
            int p = idx / 60, rem = idx - p * 60;
            int r = rem / 10, k = rem - r * 10;
            int hr = h0 - 1 + r;
            int gc = w0 - 4 + 4 * k;
            soff[i] = r * 320 + p * 40 + 4 * k;
            if (hr >= 0 && hr < Hv && gc >= 0 && gc <= Wv - 4) {
                sact[i] = true;
                sptr[i] = x + ((size_t)(bz * Cv + 2 * p) * Hv + hr) * Wv + gc;
            }
        }
    }

    float acc[8][4];
    #pragma unroll
    for (int i = 0; i < 8; i++)
        #pragma unroll
        for (int j = 0; j < 4; j++) acc[i][j] = 0.f;

    float4 v0[2], v1[2];
    auto ldx = [&](int cc) {
        #pragma unroll
        for (int i = 0; i < 2; i++) {
            float4 a = make_float4(0.f, 0.f, 0.f, 0.f);
            float4 c = make_float4(0.f, 0.f, 0.f, 0.f);
            if (sact[i]) {
                const float* src = sptr[i] + (size_t)cc * (16 * HW);
                a = *(const float4*)src;
                c = *(const float4*)(src + HW);
            }
            v0[i] = a; v1[i] = c;
        }
    };
    auto stx = [&](int buf) {
        #pragma unroll
        for (int i = 0; i < 2; i++) {
            if (sval[i]) {
                float4 a = v0[i], c = v1[i];
                uint4 H;
                H.x = hpack(a.x, c.x);
                H.y = hpack(a.y, c.y);
                H.z = hpack(a.z, c.z);
                H.w = hpack(a.w, c.w);
                *(uint4*)&xs[buf][soff[i]] = H;
            }
        }
    };

    ldx(0);
    stx(0);
    __syncthreads();                         // xs[0] + sc ready
    #pragma unroll 1
    for (int cc = 0; cc < 4; cc++) {
        const int buf = cc & 1;
        if (cc < 3) ldx(cc + 1);             // LDGs fly under the mma below

        const uint4* wb = g_wfrag + (size_t)((cc * 9) * 4 + mt) * 32 + lane;
        #pragma unroll
        for (int dw = 0; dw < 3; dw++) {
            uint4 A0 = wb[(size_t)(0 * 3 + dw) * 128];
            uint4 A1 = wb[(size_t)(1 * 3 + dw) * 128];
            uint4 A2 = wb[(size_t)(2 * 3 + dw) * 128];
            #pragma unroll
            for (int wg = 0; wg < 4; wg++) {
                const int j2 = 3 + (wg << 3) + g + dw;
                #pragma unroll
                for (int rr = 0; rr < 4; rr++) {
                    const int r = nh * 2 + rr;         // input row index 0..5
                    const uint32_t* xb = xs[buf] + r * 320 + j2;
                    uint32_t b0 = xb[tig * 40];
                    uint32_t b1 = xb[(tig + 4) * 40];
                    if (rr <= 2) {
                        uint4 A = (rr == 0) ? A0 : (rr == 1) ? A1 : A2;
                        mma_f16(acc[wg], A, b0, b1);
                    }
                    if (rr >= 1) {
                        uint4 A = (rr == 1) ? A0 : (rr == 2) ? A1 : A2;
                        mma_f16(acc[4 + wg], A, b0, b1);
                    }
                }
            }
        }
        if (cc < 3) {
            stx(buf ^ 1);
            __syncthreads();
        }
    }

    // ---- epilogue: relu( (score*inv)*fv + inv*x + (beta - mean*inv) ) ----
    const int c0 = mt * 16 + g, c1 = c0 + 8;
    const float i0 = gamma[c0] * rsqrtf(rvar[c0] + EPSV);
    const float i1 = gamma[c1] * rsqrtf(rvar[c1] + EPSV);
    const float a0 = sc[c0] * i0;
    const float a1 = sc[c1] * i1;
    const float bb0 = beta[c0] - rmean[c0] * i0;
    const float bb1 = beta[c1] - rmean[c1] * i1;
    #pragma unroll
    for (int nt = 0; nt < 8; nt++) {
        int ohl = nt >> 2, wg = nt & 3;
        int h = h0 + nh * 2 + ohl;
        int wc = w0 + (wg << 3) + 2 * tig;
        size_t o0 = ((size_t)(bz * Cv + c0) * Hv + h) * Wv + wc;
        size_t o1 = ((size_t)(bz * Cv + c1) * Hv + h) * Wv + wc;
        float2 xv0 = *(const float2*)(x + o0);
        float2 xv1 = *(const float2*)(x + o1);
        float2 r0, r1;
        r0.x = fmaxf(fmaf(a0, acc[nt][0], fmaf(i0, xv0.x, bb0)), 0.f);
        r0.y = fmaxf(fmaf(a0, acc[nt][1], fmaf(i0, xv0.y, bb0)), 0.f);
        r1.x = fmaxf(fmaf(a1, acc[nt][2], fmaf(i1, xv1.x, bb1)), 0.f);
        r1.y = fmaxf(fmaf(a1, acc[nt][3], fmaf(i1, xv1.y, bb1)), 0.f);
        *(float2*)(out + o0) = r0;
        *(float2*)(out + o1) = r1;
    }
}

// ---------------- launch ----------------
extern "C" void kernel_launch(void* const* d_in, const int* in_sizes, int n_in,
                              void* d_out, int out_size) {
    const float* x     = (const float*)d_in[0];
    const float* wq    = (const float*)d_in[1];
    const float* wk    = (const float*)d_in[2];
    const float* wv    = (const float*)d_in[3];
    const float* gamma = (const float*)d_in[4];
    const float* beta  = (const float*)d_in[5];
    const float* rmean = (const float*)d_in[6];
    const float* rvar  = (const float*)d_in[7];
    float* out = (float*)d_out;

    k_colsum_wfrag<<<1042, 256>>>(x, wv);
    k_fsum<<<dim3(Cv, Bv, 2), 128>>>(x, wq, wk);
    k_conv<<<dim3(Hv / 4, Wv / 32, Bv), 256>>>(x, gamma, beta, rmean, rvar, out);
}

// round 14
// speedup vs baseline: 1.0908x; 1.0908x over previous
#include <cuda_runtime.h>
#include <cuda_fp16.h>
#include <cstdint>

#define Bv 8
#define Cv 64
#define Hv 256
#define Wv 256
#define HW 65536
#define EPSV 1e-5f
#define XH_W 264               // 4 pad | 256 | 4 pad
#define XH_CH (256 * XH_W)     // words per (b,p) channel-pair plane

// ---------------- scratch (no allocations allowed) ----------------
__device__ float g_colsum2[2][Bv * Cv * Wv];     // h-half partial column sums
__device__ float g_fsum[Bv * Cv];
__device__ uint4 g_wfrag[4 * 9 * 4 * 32];        // fp16 A fragments
__device__ uint32_t g_xh[Bv * 32 * XH_CH];       // half2(ci=2p, ci=2p+1), w-padded

// ---------------- helpers ----------------
__device__ __forceinline__ uint32_t hpack(float lo, float hi) {
    __half2 t = __floats2half2_rn(lo, hi);
    return *reinterpret_cast<uint32_t*>(&t);
}
__device__ __forceinline__ void mma_f16(float* c, uint4 a, uint32_t b0, uint32_t b1) {
    asm volatile(
        "mma.sync.aligned.m16n8k16.row.col.f32.f16.f16.f32 "
        "{%0,%1,%2,%3}, {%4,%5,%6,%7}, {%8,%9}, {%0,%1,%2,%3};"
        : "+f"(c[0]), "+f"(c[1]), "+f"(c[2]), "+f"(c[3])
        : "r"(a.x), "r"(a.y), "r"(a.z), "r"(a.w), "r"(b0), "r"(b1));
}
__device__ __forceinline__ void cp16z(uint32_t dst, const void* src, int srcbytes) {
    asm volatile("cp.async.cg.shared.global [%0], [%1], 16, %2;"
                 :: "r"(dst), "l"(src), "r"(srcbytes));
}
__device__ __forceinline__ void cp_commit() {
    asm volatile("cp.async.commit_group;" ::: "memory");
}
__device__ __forceinline__ void cp_wait0() {
    asm volatile("cp.async.wait_group 0;" ::: "memory");
}

// ---------------- kernel 1: x -> half2 tensor + colsum partials + wfrag ----------------
// blocks [0,512): (p, b, hseg); each handles 2 channels (2p, 2p+1), 128 h rows.
// blocks [512,530): weight fragments.
__global__ void k_prep(const float* __restrict__ x, const float* __restrict__ wv) {
    if (blockIdx.x < 512) {
        int bid = blockIdx.x;
        int p = bid & 31, b = (bid >> 5) & 7, hs = bid >> 8;
        int w = threadIdx.x;
        const float* x0 = x + ((size_t)(b * Cv + 2 * p) * Hv + hs * 128) * Wv + w;
        const float* x1 = x0 + HW;
        uint32_t* dst = g_xh + ((size_t)(b * 32 + p) * Hv + hs * 128) * XH_W + 4 + w;
        float s0 = 0.f, s1 = 0.f;
        #pragma unroll 4
        for (int h = 0; h < 128; h++) {
            float a = x0[h * Wv];
            float c = x1[h * Wv];
            s0 += a; s1 += c;
            dst[h * XH_W] = hpack(a, c);
            if (w < 4) {                       // zero the w-halo pads
                dst[h * XH_W - 4 - w + (w)] = dst[h * XH_W]; // placeholder avoided below
            }
        }
        // pad columns (idx 0..3 and 260..263) zeroed by first 8 threads
        if (w < 8) {
            uint32_t* rowb = g_xh + ((size_t)(b * 32 + p) * Hv + hs * 128) * XH_W;
            int pc = (w < 4) ? w : (256 + w);   // 0..3 or 260..263
            for (int h = 0; h < 128; h++) rowb[h * XH_W + pc] = 0u;
        }
        g_colsum2[hs][(b * Cv + 2 * p) * Wv + w] = s0;
        g_colsum2[hs][(b * Cv + 2 * p + 1) * Wv + w] = s1;
    } else {
        int wid = threadIdx.x >> 5, lane = threadIdx.x & 31;
        int combo = (blockIdx.x - 512) * 8 + wid;
        int cc = combo / 36, r = combo % 36, tap = r >> 2, mt = r & 3;
        int tig = lane & 3, g = lane >> 2;
        uint32_t h[4];
        #pragma unroll
        for (int rsel = 0; rsel < 4; rsel++) {
            int row = g + (rsel & 1) * 8;
            int k = 2 * tig + (rsel >> 1) * 8;
            int cout = mt * 16 + row;
            float e0 = wv[(size_t)cout * 576 + (cc * 16 + k) * 9 + tap];
            float e1 = wv[(size_t)cout * 576 + (cc * 16 + k + 1) * 9 + tap];
            h[rsel] = hpack(e0, e1);
        }
        g_wfrag[(size_t)combo * 32 + lane] = make_uint4(h[0], h[1], h[2], h[3]);
    }
}

// ---------------- kernel 2: f_sum via row-sum identity (R11 form, partial colsums) ----
__global__ void k_fsum(const float* __restrict__ x, const float* __restrict__ wq,
                       const float* __restrict__ wk) {
    int c = blockIdx.x, b = blockIdx.y, w = threadIdx.x;
    __shared__ float wqs[576], wks[576], red[256];
    for (int i = w; i < 576; i += 256) { wqs[i] = wq[c * 576 + i]; wks[i] = wk[c * 576 + i]; }
    __syncthreads();
    float sq = 0.f, sk = 0.f;
    for (int ci = 0; ci < Cv; ci++) {
        const float* S0 = g_colsum2[0] + (b * Cv + ci) * Wv;
        const float* S1 = g_colsum2[1] + (b * Cv + ci) * Wv;
        const float* xf = x + (size_t)(b * Cv + ci) * HW;
        const float* xl = xf + (Hv - 1) * Wv;
        const float* q9 = wqs + ci * 9;
        const float* K9 = wks + ci * 9;
        #pragma unroll
        for (int dw = 0; dw < 3; dw++) {
            int wp = w + dw - 1;
            if ((unsigned)wp < (unsigned)Wv) {
                float s = S0[wp] + S1[wp], t = xl[wp], f = xf[wp];
                float q0 = q9[dw], q1 = q9[3 + dw], q2 = q9[6 + dw];
                float k0 = K9[dw], k1 = K9[3 + dw], k2 = K9[6 + dw];
                sq += s * (q0 + q1 + q2) - t * q0 - f * q2;
                sk += s * (k0 + k1 + k2) - t * k0 - f * k2;
            }
        }
    }
    red[w] = sq * sk;
    __syncthreads();
    for (int s = 128; s > 0; s >>= 1) { if (w < s) red[w] += red[w + s]; __syncthreads(); }
    if (w == 0) g_fsum[b * Cv + c] = red[0] * 0.0625f;
}

// ---------------- kernel 3: fp16 mma conv, cp.async-fed + softmax + epilogue ----------------
// CTA: b x (4 out rows) x (32 out cols). xs layout identical to R11:
// word(r, p, j-chunk k, q) = r*320 + p*40 + 4k + q. Tiles arrive via cp.async
// from the pre-converted g_xh (w-halo prepadded; h-halo via zfill).
__global__ void __launch_bounds__(256, 4)
k_conv(const float* __restrict__ x,
       const float* __restrict__ gamma, const float* __restrict__ beta,
       const float* __restrict__ rmean, const float* __restrict__ rvar,
       float* __restrict__ out) {
    __shared__ uint32_t xs[2][1920];
    __shared__ float sc[64];
    const int tid = threadIdx.x;
    const int lane = tid & 31, wid = tid >> 5;
    const int tig = lane & 3, g = lane >> 2;
    const int mt = wid >> 1, nh = wid & 1;
    const int h0 = blockIdx.x * 4;
    const int w0 = blockIdx.y * 32;
    const int bz = blockIdx.z;

    // ---- inline softmax over 64 channels (warp 0) ----
    if (wid == 0) {
        float va = g_fsum[bz * Cv + lane];
        float vb = g_fsum[bz * Cv + 32 + lane];
        float m = fmaxf(va, vb);
        #pragma unroll
        for (int off = 16; off > 0; off >>= 1)
            m = fmaxf(m, __shfl_xor_sync(0xFFFFFFFFu, m, off));
        float ea = expf(va - m), eb = expf(vb - m);
        float s = ea + eb;
        #pragma unroll
        for (int off = 16; off > 0; off >>= 1)
            s += __shfl_xor_sync(0xFFFFFFFFu, s, off);
        sc[lane] = ea / s;
        sc[lane + 32] = eb / s;
    }

    // ---- cp.async slot geometry (2 slots/thread; hoisted) ----
    const uint32_t* gsrc[2];
    uint32_t sdst[2];
    int ssz[2];
    #pragma unroll
    for (int i = 0; i < 2; i++) {
        int idx = tid + 256 * i;
        ssz[i] = -1;                      // inactive
        gsrc[i] = g_xh;
        sdst[i] = 0;
        if (idx < 480) {
            int p = idx / 60, rem = idx - p * 60;
            int r = rem / 10, k = rem - r * 10;
            int hr = h0 - 1 + r;
            int hsafe = (hr < 0) ? 0 : (hr > 255 ? 255 : hr);
            ssz[i] = (hr >= 0 && hr < Hv) ? 16 : 0;
            gsrc[i] = g_xh + ((size_t)(bz * 32 + p) * Hv + hsafe) * XH_W + (w0 + 4 * k);
            sdst[i] = (uint32_t)__cvta_generic_to_shared(&xs[0][r * 320 + p * 40 + 4 * k]);
        }
    }
    auto issue = [&](int buf, int cc) {
        const uint32_t bufoff = (uint32_t)buf * 7680;        // bytes
        const size_t ccoff = (size_t)cc * 8 * XH_CH;         // +8 channel pairs
        #pragma unroll
        for (int i = 0; i < 2; i++) {
            if (ssz[i] >= 0) cp16z(sdst[i] + bufoff, gsrc[i] + ccoff, ssz[i]);
        }
        cp_commit();
    };

    float acc[8][4];
    #pragma unroll
    for (int i = 0; i < 8; i++)
        #pragma unroll
        for (int j = 0; j < 4; j++) acc[i][j] = 0.f;

    issue(0, 0);
    cp_wait0();
    __syncthreads();                         // xs[0] + sc ready
    #pragma unroll 1
    for (int cc = 0; cc < 4; cc++) {
        const int buf = cc & 1;
        if (cc < 3) issue(buf ^ 1, cc + 1);  // async fill flies under the MMAs

        const uint4* wb = g_wfrag + (size_t)((cc * 9) * 4 + mt) * 32 + lane;
        #pragma unroll
        for (int dw = 0; dw < 3; dw++) {
            uint4 A0 = wb[(size_t)(0 * 3 + dw) * 128];
            uint4 A1 = wb[(size_t)(1 * 3 + dw) * 128];
            uint4 A2 = wb[(size_t)(2 * 3 + dw) * 128];
            #pragma unroll
            for (int wg = 0; wg < 4; wg++) {
                const int j2 = 3 + (wg << 3) + g + dw;
                #pragma unroll
                for (int rr = 0; rr < 4; rr++) {
                    const int r = nh * 2 + rr;          // input row 0..5
                    const uint32_t* xb = xs[buf] + r * 320 + j2;
                    uint32_t b0 = xb[tig * 40];
                    uint32_t b1 = xb[(tig + 4) * 40];
                    if (rr <= 2) {
                        uint4 A = (rr == 0) ? A0 : (rr == 1) ? A1 : A2;
                        mma_f16(acc[wg], A, b0, b1);
                    }
                    if (rr >= 1) {
                        uint4 A = (rr == 1) ? A0 : (rr == 2) ? A1 : A2;
                        mma_f16(acc[4 + wg], A, b0, b1);
                    }
                }
            }
        }
        if (cc < 3) {
            cp_wait0();                      // own copies done (had whole MMA to land)
            __syncthreads();                 // everyone's copies visible
        }
    }

    // ---- epilogue: relu( (score*inv)*fv + inv*x + (beta - mean*inv) ) ----
    const int c0 = mt * 16 + g, c1 = c0 + 8;
    const float i0 = gamma[c0] * rsqrtf(rvar[c0] + EPSV);
    const float i1 = gamma[c1] * rsqrtf(rvar[c1] + EPSV);
    const float a0 = sc[c0] * i0;
    const float a1 = sc[c1] * i1;
    const float bb0 = beta[c0] - rmean[c0] * i0;
    const float bb1 = beta[c1] - rmean[c1] * i1;
    #pragma unroll
    for (int nt = 0; nt < 8; nt++) {
        int ohl = nt >> 2, wg = nt & 3;
        int h = h0 + nh * 2 + ohl;
        int wc = w0 + (wg << 3) + 2 * tig;
        size_t o0 = ((size_t)(bz * Cv + c0) * Hv + h) * Wv + wc;
        size_t o1 = ((size_t)(bz * Cv + c1) * Hv + h) * Wv + wc;
        float2 xv0 = *(const float2*)(x + o0);
        float2 xv1 = *(const float2*)(x + o1);
        float2 r0, r1;
        r0.x = fmaxf(fmaf(a0, acc[nt][0], fmaf(i0, xv0.x, bb0)), 0.f);
        r0.y = fmaxf(fmaf(a0, acc[nt][1], fmaf(i0, xv0.y, bb0)), 0.f);
        r1.x = fmaxf(fmaf(a1, acc[nt][2], fmaf(i1, xv1.x, bb1)), 0.f);
        r1.y = fmaxf(fmaf(a1, acc[nt][3], fmaf(i1, xv1.y, bb1)), 0.f);
        *(float2*)(out + o0) = r0;
        *(float2*)(out + o1) = r1;
    }
}

// ---------------- launch ----------------
extern "C" void kernel_launch(void* const* d_in, const int* in_sizes, int n_in,
                              void* d_out, int out_size) {
    const float* x     = (const float*)d_in[0];
    const float* wq    = (const float*)d_in[1];
    const float* wk    = (const float*)d_in[2];
    const float* wv    = (const float*)d_in[3];
    const float* gamma = (const float*)d_in[4];
    const float* beta  = (const float*)d_in[5];
    const float* rmean = (const float*)d_in[6];
    const float* rvar  = (const float*)d_in[7];
    float* out = (float*)d_out;

    k_prep<<<530, 256>>>(x, wv);
    k_fsum<<<dim3(Cv, Bv), 256>>>(x, wq, wk);
    k_conv<<<dim3(Hv / 4, Wv / 32, Bv), 256>>>(x, gamma, beta, rmean, rvar, out);
}

// round 15
// speedup vs baseline: 1.1133x; 1.0207x over previous
#include <cuda_runtime.h>
#include <cuda_fp16.h>
#include <cstdint>

#define Bv 8
#define Cv 64
#define Hv 256
#define Wv 256
#define HW 65536
#define EPSV 1e-5f
#define XH_W 264               // 4 pad | 256 | 4 pad
#define XH_CH (256 * XH_W)     // words per (b,p) channel-pair plane
#define NFSUM 512
#define NCONV 4096
#define GRID2 (NFSUM + NCONV)

// ---------------- scratch (no allocations allowed) ----------------
__device__ float g_colsum4[4][Bv * Cv * Wv];     // h-quarter partial column sums
__device__ float g_fsum[Bv * Cv];
__device__ uint4 g_wfrag[4 * 9 * 4 * 32];        // fp16 A fragments
__device__ uint32_t g_xh[Bv * 32 * XH_CH];       // half2(ci=2p, ci=2p+1), w-padded
__device__ int c_fsum;                            // fsum blocks completed
__device__ int c_done;                            // ticket counter (reset protocol)

// ---------------- helpers ----------------
__device__ __forceinline__ uint32_t hpack(float lo, float hi) {
    __half2 t = __floats2half2_rn(lo, hi);
    return *reinterpret_cast<uint32_t*>(&t);
}
__device__ __forceinline__ void mma_f16(float* c, uint4 a, uint32_t b0, uint32_t b1) {
    asm volatile(
        "mma.sync.aligned.m16n8k16.row.col.f32.f16.f16.f32 "
        "{%0,%1,%2,%3}, {%4,%5,%6,%7}, {%8,%9}, {%0,%1,%2,%3};"
        : "+f"(c[0]), "+f"(c[1]), "+f"(c[2]), "+f"(c[3])
        : "r"(a.x), "r"(a.y), "r"(a.z), "r"(a.w), "r"(b0), "r"(b1));
}
__device__ __forceinline__ void cp16z(uint32_t dst, const void* src, int srcbytes) {
    asm volatile("cp.async.cg.shared.global [%0], [%1], 16, %2;"
                 :: "r"(dst), "l"(src), "r"(srcbytes));
}
__device__ __forceinline__ void cp_commit() {
    asm volatile("cp.async.commit_group;" ::: "memory");
}
__device__ __forceinline__ void cp_wait0() {
    asm volatile("cp.async.wait_group 0;" ::: "memory");
}
__device__ __forceinline__ int gload_acq(int* p) {
    int v;
    asm volatile("ld.global.acquire.gpu.b32 %0, [%1];" : "=r"(v) : "l"(p) : "memory");
    return v;
}
__device__ __forceinline__ void spin_until(int* p, int target) {
    while (gload_acq(p) < target) __nanosleep(64);
}

// ---------------- kernel 1: x -> half2 tensor + colsum quarters + wfrag ----------------
// blocks [0,1024): (p, b, hq); 2 channels (2p, 2p+1), 64 h rows each.
// blocks [1024,1042): weight fragments (18 blocks x 8 warps = 144 combos).
__global__ void k_prep(const float* __restrict__ x, const float* __restrict__ wv) {
    if (blockIdx.x < 1024) {
        int bid = blockIdx.x;
        int p = bid & 31, b = (bid >> 5) & 7, hq = bid >> 8;
        int w = threadIdx.x;
        const float* x0 = x + ((size_t)(b * Cv + 2 * p) * Hv + hq * 64) * Wv + w;
        const float* x1 = x0 + HW;
        uint32_t* rowb = g_xh + ((size_t)(b * 32 + p) * Hv + hq * 64) * XH_W;
        uint32_t* dst = rowb + 4 + w;
        float s0 = 0.f, s1 = 0.f;
        #pragma unroll 4
        for (int h = 0; h < 64; h++) {
            float a = x0[h * Wv];
            float c = x1[h * Wv];
            s0 += a; s1 += c;
            dst[h * XH_W] = hpack(a, c);
        }
        // pad columns (0..3 and 260..263) zeroed; unique (thread,row) addresses
        if (w < 8) {
            int pc = (w < 4) ? w : (256 + w);   // 0..3 or 260..263
            for (int h = 0; h < 64; h++) rowb[h * XH_W + pc] = 0u;
        }
        g_colsum4[hq][(b * Cv + 2 * p) * Wv + w] = s0;
        g_colsum4[hq][(b * Cv + 2 * p + 1) * Wv + w] = s1;
    } else {
        int wid = threadIdx.x >> 5, lane = threadIdx.x & 31;
        int combo = (blockIdx.x - 1024) * 8 + wid;
        int cc = combo / 36, r = combo % 36, tap = r >> 2, mt = r & 3;
        int tig = lane & 3, g = lane >> 2;
        uint32_t h[4];
        #pragma unroll
        for (int rsel = 0; rsel < 4; rsel++) {
            int row = g + (rsel & 1) * 8;
            int k = 2 * tig + (rsel >> 1) * 8;
            int cout = mt * 16 + row;
            float e0 = wv[(size_t)cout * 576 + (cc * 16 + k) * 9 + tap];
            float e1 = wv[(size_t)cout * 576 + (cc * 16 + k + 1) * 9 + tap];
            h[rsel] = hpack(e0, e1);
        }
        g_wfrag[(size_t)combo * 32 + lane] = make_uint4(h[0], h[1], h[2], h[3]);
    }
}

// ---------------- kernel 2: fsum (blocks 0..511) + conv (blocks 512..4607) ----------------
// fsum blocks never wait (colsum ready at kernel boundary); they retire and free
// slots. conv blocks wait on c_fsum only in the EPILOGUE (producer guaranteed
// scheduled first: lower bids). Counters reset by last c_done ticket.
__global__ void __launch_bounds__(256, 4)
k_main(const float* __restrict__ x,
       const float* __restrict__ wq, const float* __restrict__ wk,
       const float* __restrict__ gamma, const float* __restrict__ beta,
       const float* __restrict__ rmean, const float* __restrict__ rvar,
       float* __restrict__ out) {
    __shared__ __align__(16) char smb[15616];
    const int bid = blockIdx.x;
    const int tid = threadIdx.x;
    const int lane = tid & 31, wid = tid >> 5;

    if (bid < NFSUM) {
        // ---------------- role: fsum via row-sum identity ----------------
        float* wqs = (float*)smb;                  // 576
        float* wks = (float*)(smb + 2304);         // 576
        float* red = (float*)(smb + 4608);         // 256
        int c = bid & 63, b = bid >> 6;
        int w = tid;
        for (int i = w; i < 576; i += 256) {
            wqs[i] = wq[c * 576 + i];
            wks[i] = wk[c * 576 + i];
        }
        __syncthreads();
        float sq = 0.f, sk = 0.f;
        for (int ci = 0; ci < Cv; ci++) {
            const float* S0 = g_colsum4[0] + (b * Cv + ci) * Wv;
            const float* S1 = g_colsum4[1] + (b * Cv + ci) * Wv;
            const float* S2 = g_colsum4[2] + (b * Cv + ci) * Wv;
            const float* S3 = g_colsum4[3] + (b * Cv + ci) * Wv;
            const float* xf = x + (size_t)(b * Cv + ci) * HW;
            const float* xl = xf + (Hv - 1) * Wv;
            const float* q9 = wqs + ci * 9;
            const float* K9 = wks + ci * 9;
            #pragma unroll
            for (int dw = 0; dw < 3; dw++) {
                int wp = w + dw - 1;
                if ((unsigned)wp < (unsigned)Wv) {
                    float s = (S0[wp] + S1[wp]) + (S2[wp] + S3[wp]);
                    float t = xl[wp], f = xf[wp];
                    float q0 = q9[dw], q1 = q9[3 + dw], q2 = q9[6 + dw];
                    float k0 = K9[dw], k1 = K9[3 + dw], k2 = K9[6 + dw];
                    sq += s * (q0 + q1 + q2) - t * q0 - f * q2;
                    sk += s * (k0 + k1 + k2) - t * k0 - f * k2;
                }
            }
        }
        red[w] = sq * sk;
        __syncthreads();
        for (int s = 128; s > 0; s >>= 1) {
            if (w < s) red[w] += red[w + s];
            __syncthreads();
        }
        if (w == 0) {
            g_fsum[b * Cv + c] = red[0] * 0.0625f;   // 1/sqrt(256)
            __threadfence();
            atomicAdd(&c_fsum, 1);
            int t = atomicAdd(&c_done, 1);
            if (t == GRID2 - 1) { c_fsum = 0; c_done = 0; }
        }
        return;
    }

    // ---------------- role: conv (fp16 mma, cp.async-fed from g_xh) ----------------
    uint32_t* xsb = (uint32_t*)smb;               // [2][1920]
    float* sc = (float*)(smb + 15360);            // 64 floats
    const int bid2 = bid - NFSUM;
    const int ht = bid2 & 63;
    const int wt = (bid2 >> 6) & 7;
    const int bz = bid2 >> 9;
    const int h0 = ht * 4;
    const int w0 = wt * 32;
    const int tig = lane & 3, g = lane >> 2;
    const int mt = wid >> 1, nh = wid & 1;

    // ---- cp.async slot geometry (2 slots/thread; hoisted) ----
    const uint32_t* gsrc[2];
    uint32_t sdst[2];
    int ssz[2];
    #pragma unroll
    for (int i = 0; i < 2; i++) {
        int idx = tid + 256 * i;
        ssz[i] = -1;
        gsrc[i] = g_xh;
        sdst[i] = 0;
        if (idx < 480) {
            int p = idx / 60, rem = idx - p * 60;
            int r = rem / 10, k = rem - r * 10;
            int hr = h0 - 1 + r;
            int hsafe = (hr < 0) ? 0 : (hr > 255 ? 255 : hr);
            ssz[i] = (hr >= 0 && hr < Hv) ? 16 : 0;
            gsrc[i] = g_xh + ((size_t)(bz * 32 + p) * Hv + hsafe) * XH_W + (w0 + 4 * k);
            sdst[i] = (uint32_t)__cvta_generic_to_shared(&xsb[r * 320 + p * 40 + 4 * k]);
        }
    }
    auto issue = [&](int buf, int cc) {
        const uint32_t bufoff = (uint32_t)buf * 7680;        // bytes
        const size_t ccoff = (size_t)cc * 8 * XH_CH;         // +8 channel pairs
        #pragma unroll
        for (int i = 0; i < 2; i++) {
            if (ssz[i] >= 0) cp16z(sdst[i] + bufoff, gsrc[i] + ccoff, ssz[i]);
        }
        cp_commit();
    };

    float acc[8][4];
    #pragma unroll
    for (int i = 0; i < 8; i++)
        #pragma unroll
        for (int j = 0; j < 4; j++) acc[i][j] = 0.f;

    issue(0, 0);
    cp_wait0();
    __syncthreads();
    #pragma unroll 1
    for (int cc = 0; cc < 4; cc++) {
        const int buf = cc & 1;
        if (cc < 3) issue(buf ^ 1, cc + 1);

        const uint4* wb = g_wfrag + (size_t)((cc * 9) * 4 + mt) * 32 + lane;
        #pragma unroll
        for (int dw = 0; dw < 3; dw++) {
            uint4 A0 = wb[(size_t)(0 * 3 + dw) * 128];
            uint4 A1 = wb[(size_t)(1 * 3 + dw) * 128];
            uint4 A2 = wb[(size_t)(2 * 3 + dw) * 128];
            #pragma unroll
            for (int wg = 0; wg < 4; wg++) {
                const int j2 = 3 + (wg << 3) + g + dw;
                #pragma unroll
                for (int rr = 0; rr < 4; rr++) {
                    const int r = nh * 2 + rr;
                    const uint32_t* xb = xsb + buf * 1920 + r * 320 + j2;
                    uint32_t b0 = xb[tig * 40];
                    uint32_t b1 = xb[(tig + 4) * 40];
                    if (rr <= 2) {
                        uint4 A = (rr == 0) ? A0 : (rr == 1) ? A1 : A2;
                        mma_f16(acc[wg], A, b0, b1);
                    }
                    if (rr >= 1) {
                        uint4 A = (rr == 1) ? A0 : (rr == 2) ? A1 : A2;
                        mma_f16(acc[4 + wg], A, b0, b1);
                    }
                }
            }
        }
        if (cc < 3) {
            cp_wait0();
            __syncthreads();
        }
    }

    // ---- wait for fsum, then in-block softmax ----
    if (tid == 0) spin_until(&c_fsum, NFSUM);
    __syncthreads();
    if (wid == 0) {
        float va = g_fsum[bz * Cv + lane];
        float vb = g_fsum[bz * Cv + 32 + lane];
        float m = fmaxf(va, vb);
        #pragma unroll
        for (int off = 16; off > 0; off >>= 1)
            m = fmaxf(m, __shfl_xor_sync(0xFFFFFFFFu, m, off));
        float ea = expf(va - m), eb = expf(vb - m);
        float s = ea + eb;
        #pragma unroll
        for (int off = 16; off > 0; off >>= 1)
            s += __shfl_xor_sync(0xFFFFFFFFu, s, off);
        sc[lane] = ea / s;
        sc[lane + 32] = eb / s;
    }
    __syncthreads();

    // ---- epilogue: relu( (score*inv)*fv + inv*x + (beta - mean*inv) ) ----
    const int c0 = mt * 16 + g, c1 = c0 + 8;
    const float i0 = gamma[c0] * rsqrtf(rvar[c0] + EPSV);
    const float i1 = gamma[c1] * rsqrtf(rvar[c1] + EPSV);
    const float a0 = sc[c0] * i0;
    const float a1 = sc[c1] * i1;
    const float bb0 = beta[c0] - rmean[c0] * i0;
    const float bb1 = beta[c1] - rmean[c1] * i1;
    #pragma unroll
    for (int nt = 0; nt < 8; nt++) {
        int ohl = nt >> 2, wg = nt & 3;
        int h = h0 + nh * 2 + ohl;
        int wc = w0 + (wg << 3) + 2 * tig;
        size_t o0 = ((size_t)(bz * Cv + c0) * Hv + h) * Wv + wc;
        size_t o1 = ((size_t)(bz * Cv + c1) * Hv + h) * Wv + wc;
        float2 xv0 = *(const float2*)(x + o0);
        float2 xv1 = *(const float2*)(x + o1);
        float2 r0, r1;
        r0.x = fmaxf(fmaf(a0, acc[nt][0], fmaf(i0, xv0.x, bb0)), 0.f);
        r0.y = fmaxf(fmaf(a0, acc[nt][1], fmaf(i0, xv0.y, bb0)), 0.f);
        r1.x = fmaxf(fmaf(a1, acc[nt][2], fmaf(i1, xv1.x, bb1)), 0.f);
        r1.y = fmaxf(fmaf(a1, acc[nt][3], fmaf(i1, xv1.y, bb1)), 0.f);
        *(float2*)(out + o0) = r0;
        *(float2*)(out + o1) = r1;
    }

    if (tid == 0) {
        int t = atomicAdd(&c_done, 1);
        if (t == GRID2 - 1) { c_fsum = 0; c_done = 0; }
    }
}

// ---------------- launch ----------------
extern "C" void kernel_launch(void* const* d_in, const int* in_sizes, int n_in,
                              void* d_out, int out_size) {
    const float* x     = (const float*)d_in[0];
    const float* wq    = (const float*)d_in[1];
    const float* wk    = (const float*)d_in[2];
    const float* wv    = (const float*)d_in[3];
    const float* gamma = (const float*)d_in[4];
    const float* beta  = (const float*)d_in[5];
    const float* rmean = (const float*)d_in[6];
    const float* rvar  = (const float*)d_in[7];
    float* out = (float*)d_out;

    k_prep<<<1042, 256>>>(x, wv);
    k_main<<<GRID2, 256>>>(x, wq, wk, gamma, beta, rmean, rvar, out);
}